// round 2
// baseline (speedup 1.0000x reference)
#include <cuda_runtime.h>
#include <cstdint>
#include <math.h>

#define BATCH   2
#define SEQL    1024
#define DMODEL  768
#define DINNER  1536
#define DSTATE  16
#define DCONV   4
#define DTRANK  48
#define MTOT    (BATCH*SEQL)              /* 2048 */
#define TOTOUT  52272
#define OFF_U   DINNER                    /* 1536 */
#define OFF_DTH (2*DINNER)                /* 3072 */
#define OFF_B   (2*DINNER + DTRANK)       /* 3120 */
#define OFF_C   (OFF_B + DINNER*DSTATE)   /* 27696 */

/* ------------------- scratch (static device allocations) ------------------- */
__device__ float g_xn [MTOT * DMODEL];
__device__ float g_p  [(size_t)MTOT * TOTOUT];
__device__ float g_dtl[MTOT * DINNER];
__device__ float g_dt [MTOT * DINNER];
__device__ float g_uc [MTOT * DINNER];
__device__ float g_y  [MTOT * DINNER];
__device__ float g_res[MTOT * DINNER];
__device__ float g_g  [MTOT * DINNER];

/* ------------------------------- helpers ----------------------------------- */
__device__ __forceinline__ unsigned f2tf32(float x) {
    unsigned u;
    asm("cvt.rna.tf32.f32 %0, %1;" : "=r"(u) : "f"(x));
    return u;
}

__device__ __forceinline__ void mma_tf32(float* c, const unsigned* a, const unsigned* b) {
    asm volatile(
        "mma.sync.aligned.m16n8k8.row.col.f32.tf32.tf32.f32 "
        "{%0,%1,%2,%3}, {%4,%5,%6,%7}, {%8,%9}, {%0,%1,%2,%3};"
        : "+f"(c[0]), "+f"(c[1]), "+f"(c[2]), "+f"(c[3])
        : "r"(a[0]), "r"(a[1]), "r"(a[2]), "r"(a[3]),
          "r"(b[0]), "r"(b[1]));
}

__device__ __forceinline__ void cp16(float* smem, const float* g, int bytes) {
    unsigned sa = (unsigned)__cvta_generic_to_shared(smem);
    asm volatile("cp.async.cg.shared.global [%0], [%1], 16, %2;\n"
                 :: "r"(sa), "l"(g), "r"(bytes));
}

__device__ __forceinline__ float block_sum256(float v, float* sm) {
    int tid = threadIdx.x;
    #pragma unroll
    for (int o = 16; o; o >>= 1) v += __shfl_down_sync(0xffffffffu, v, o);
    if ((tid & 31) == 0) sm[tid >> 5] = v;
    __syncthreads();
    if (tid < 32) {
        float r = (tid < 8) ? sm[tid] : 0.f;
        #pragma unroll
        for (int o = 4; o; o >>= 1) r += __shfl_down_sync(0xffffffffu, r, o);
        if (tid == 0) sm[0] = r;
    }
    __syncthreads();
    float r = sm[0];
    __syncthreads();
    return r;
}

/* ------------------------------ layernorm ---------------------------------- */
__global__ void ln_kernel(const float* __restrict__ x, const float* __restrict__ w,
                          const float* __restrict__ bb, float* __restrict__ out) {
    __shared__ float sm[8];
    int m = blockIdx.x, tid = threadIdx.x;
    const float* row = x + (size_t)m * DMODEL;
    float v0 = row[tid], v1 = row[tid + 256], v2 = row[tid + 512];
    float s = block_sum256(v0 + v1 + v2, sm);
    float mu = s * (1.f / (float)DMODEL);
    float d0 = v0 - mu, d1 = v1 - mu, d2 = v2 - mu;
    float q = block_sum256(d0 * d0 + d1 * d1 + d2 * d2, sm);
    float inv = rsqrtf(q * (1.f / (float)DMODEL) + 1e-5f);
    float* o = out + (size_t)m * DMODEL;
    o[tid]       = d0 * inv * w[tid]       + bb[tid];
    o[tid + 256] = d1 * inv * w[tid + 256] + bb[tid + 256];
    o[tid + 512] = d2 * inv * w[tid + 512] + bb[tid + 512];
}

/* ----------------------- generic tf32 tensor-core GEMM ---------------------
   C[M,N] = A[M,K] * B[N,K]^T     (A row-major lda, B row-major ldb, C ldc)
   M % 128 == 0, K % 16 == 0, N % 8 == 0 required (all our shapes comply).  */
__global__ __launch_bounds__(256, 1)
void gemm_tf32(const float* __restrict__ A, const float* __restrict__ B,
               float* __restrict__ C, int M, int N, int K,
               int lda, int ldb, int ldc)
{
    constexpr int ST = 20;                 /* 16 + 4 pad: conflict-free frag loads */
    __shared__ float sA[2][128 * ST];
    __shared__ float sB[2][128 * ST];

    const int tid  = threadIdx.x;
    const int lane = tid & 31;
    const int warp = tid >> 5;
    const int wm   = (warp & 1) * 64;
    const int wn   = (warp >> 1) * 32;
    const int bm0  = blockIdx.y * 128;
    const int bn0  = blockIdx.x * 128;

    const int lrow = tid >> 2;             /* 0..63  */
    const int lcol = (tid & 3) * 4;        /* 0..12  */

    const float* gA1 = A + (size_t)(bm0 + lrow) * lda + lcol;
    const float* gA2 = gA1 + (size_t)64 * lda;
    int nr1 = bn0 + lrow, nr2 = bn0 + lrow + 64;
    const float* gB1 = B + (size_t)(nr1 < N ? nr1 : N - 1) * ldb + lcol;
    const float* gB2 = B + (size_t)(nr2 < N ? nr2 : N - 1) * ldb + lcol;
    const int bs1 = (nr1 < N) ? 16 : 0;
    const int bs2 = (nr2 < N) ? 16 : 0;

    float acc[4][4][4];
    #pragma unroll
    for (int i = 0; i < 4; i++)
        #pragma unroll
        for (int j = 0; j < 4; j++)
            #pragma unroll
            for (int k = 0; k < 4; k++) acc[i][j][k] = 0.f;

    auto load_stage = [&](int s, int kt) {
        int k0 = kt * 16;
        cp16(&sA[s][lrow * ST + lcol],        gA1 + k0, 16);
        cp16(&sA[s][(lrow + 64) * ST + lcol], gA2 + k0, 16);
        cp16(&sB[s][lrow * ST + lcol],        gB1 + k0, bs1);
        cp16(&sB[s][(lrow + 64) * ST + lcol], gB2 + k0, bs2);
    };

    auto compute_stage = [&](int s) {
        #pragma unroll
        for (int ks = 0; ks < 2; ks++) {
            const int k0 = ks * 8;
            unsigned au[4][4], bu[4][2];
            #pragma unroll
            for (int mi = 0; mi < 4; mi++) {
                int r = wm + mi * 16 + (lane >> 2);
                int c = k0 + (lane & 3);
                au[mi][0] = f2tf32(sA[s][r * ST + c]);
                au[mi][1] = f2tf32(sA[s][(r + 8) * ST + c]);
                au[mi][2] = f2tf32(sA[s][r * ST + c + 4]);
                au[mi][3] = f2tf32(sA[s][(r + 8) * ST + c + 4]);
            }
            #pragma unroll
            for (int nj = 0; nj < 4; nj++) {
                int nr = wn + nj * 8 + (lane >> 2);
                int kc = k0 + (lane & 3);
                bu[nj][0] = f2tf32(sB[s][nr * ST + kc]);
                bu[nj][1] = f2tf32(sB[s][nr * ST + kc + 4]);
            }
            #pragma unroll
            for (int mi = 0; mi < 4; mi++)
                #pragma unroll
                for (int nj = 0; nj < 4; nj++)
                    mma_tf32(acc[mi][nj], au[mi], bu[nj]);
        }
    };

    const int nk = K / 16;
    load_stage(0, 0);
    asm volatile("cp.async.commit_group;");
    for (int kt = 0; kt < nk; kt++) {
        if (kt + 1 < nk) load_stage((kt + 1) & 1, kt + 1);
        asm volatile("cp.async.commit_group;");
        asm volatile("cp.async.wait_group 1;");
        __syncthreads();
        compute_stage(kt & 1);
        __syncthreads();
    }

    #pragma unroll
    for (int mi = 0; mi < 4; mi++) {
        #pragma unroll
        for (int nj = 0; nj < 4; nj++) {
            int row = bm0 + wm + mi * 16 + (lane >> 2);
            int col = bn0 + wn + nj * 8 + (lane & 3) * 2;
            if (col < N) {
                float2 v0 = make_float2(acc[mi][nj][0], acc[mi][nj][1]);
                float2 v1 = make_float2(acc[mi][nj][2], acc[mi][nj][3]);
                *(float2*)(C + (size_t)row * ldc + col)       = v0;
                *(float2*)(C + (size_t)(row + 8) * ldc + col) = v1;
            }
        }
    }
}

/* ------------- softplus(dt) + clip, and causal depthwise conv -------------- */
__global__ void prep_kernel(const float* __restrict__ p, const float* __restrict__ dtl,
                            const float* __restrict__ dt_bias, const float* __restrict__ conv_w,
                            const float* __restrict__ conv_b,
                            float* __restrict__ dt_out, float* __restrict__ uc_out)
{
    int m = blockIdx.x, tid = threadIdx.x;
    int l = m & (SEQL - 1);
    #pragma unroll
    for (int i = 0; i < 6; i++) {
        int d = tid + i * 256;
        float xv = dtl[(size_t)m * DINNER + d] + dt_bias[d];
        float sp = (xv > 20.f) ? xv : log1pf(expf(xv));
        dt_out[(size_t)m * DINNER + d] = fminf(fmaxf(sp, 1e-4f), 1.0f);

        float4 cw = *(const float4*)(conv_w + d * 4);
        const float* up = p + OFF_U + d;
        float u0 = (l >= 3) ? up[(size_t)(m - 3) * TOTOUT] : 0.f;
        float u1 = (l >= 2) ? up[(size_t)(m - 2) * TOTOUT] : 0.f;
        float u2 = (l >= 1) ? up[(size_t)(m - 1) * TOTOUT] : 0.f;
        float u3 =            up[(size_t)m * TOTOUT];
        float acc = conv_b[d] + cw.x * u0 + cw.y * u1 + cw.z * u2 + cw.w * u3;
        uc_out[(size_t)m * DINNER + d] = acc;
    }
}

/* ------------------------------ selective scan ----------------------------- */
__global__ void scan_kernel(const float* __restrict__ p, const float* __restrict__ dt,
                            const float* __restrict__ uc, const float* __restrict__ A_log,
                            const float* __restrict__ Dskip, float* __restrict__ y)
{
    int t = blockIdx.x * blockDim.x + threadIdx.x;   /* 12288 = 3072 chains * 4 */
    int chain = t >> 2, part = t & 3;
    int b = chain / DINNER;
    int d = chain - b * DINNER;
    int n0 = part * 4;

    float a0 = -__expf(A_log[d * DSTATE + n0 + 0]);
    float a1 = -__expf(A_log[d * DSTATE + n0 + 1]);
    float a2 = -__expf(A_log[d * DSTATE + n0 + 2]);
    float a3 = -__expf(A_log[d * DSTATE + n0 + 3]);
    float dsk = Dskip[d];

    size_t basep = (size_t)b * SEQL * TOTOUT;
    const float* pB = p + basep + OFF_B + d * DSTATE + n0;
    const float* pC = p + basep + OFF_C + d * DSTATE + n0;
    size_t base2 = (size_t)b * SEQL * DINNER + d;
    const float* pdt = dt + base2;
    const float* puc = uc + base2;
    float* py = y + base2;

    float4 Bb[8], Cb[8];
    float dtb[8], ucb[8];
    #pragma unroll
    for (int s = 0; s < 8; s++) {
        Bb[s]  = *(const float4*)(pB + (size_t)s * TOTOUT);
        Cb[s]  = *(const float4*)(pC + (size_t)s * TOTOUT);
        dtb[s] = pdt[(size_t)s * DINNER];
        ucb[s] = puc[(size_t)s * DINNER];
    }

    float h0 = 0.f, h1 = 0.f, h2 = 0.f, h3 = 0.f;
    #pragma unroll 8
    for (int l = 0; l < SEQL; l++) {
        int slot = l & 7;
        float dtv = dtb[slot], ucv = ucb[slot];
        float4 Bv = Bb[slot], Cv = Cb[slot];
        int lp = l + 8;
        if (lp < SEQL) {
            Bb[slot]  = *(const float4*)(pB + (size_t)lp * TOTOUT);
            Cb[slot]  = *(const float4*)(pC + (size_t)lp * TOTOUT);
            dtb[slot] = pdt[(size_t)lp * DINNER];
            ucb[slot] = puc[(size_t)lp * DINNER];
        }
        float dtu = dtv * ucv;
        float e0 = __expf(dtv * a0);
        float e1 = __expf(dtv * a1);
        float e2 = __expf(dtv * a2);
        float e3 = __expf(dtv * a3);
        h0 = fmaf(h0, e0, dtu * Bv.x);
        h1 = fmaf(h1, e1, dtu * Bv.y);
        h2 = fmaf(h2, e2, dtu * Bv.z);
        h3 = fmaf(h3, e3, dtu * Bv.w);
        float acc = Cv.x * h0 + Cv.y * h1 + Cv.z * h2 + Cv.w * h3;
        acc += __shfl_down_sync(0xffffffffu, acc, 2, 4);
        acc += __shfl_down_sync(0xffffffffu, acc, 1, 4);
        if (part == 0) py[(size_t)l * DINNER] = fmaf(ucv, dsk, acc);
    }
}

/* -------------------- gating * silu(z) + RMS norm + residual --------------- */
__global__ void gate_kernel(const float* __restrict__ y, const float* __restrict__ p,
                            const float* __restrict__ norm_w, const float* __restrict__ res,
                            float* __restrict__ g)
{
    __shared__ float sm[8];
    int m = blockIdx.x, tid = threadIdx.x;
    float gv[6];
    float ss = 0.f;
    #pragma unroll
    for (int i = 0; i < 6; i++) {
        int d = tid + i * 256;
        float z  = p[(size_t)m * TOTOUT + d];        /* z block at offset 0 */
        float yv = y[(size_t)m * DINNER + d];
        float sg = 1.f / (1.f + __expf(-z));
        gv[i] = yv * z * sg;
        ss += gv[i] * gv[i];
    }
    float tot = block_sum256(ss, sm);
    float r = rsqrtf(tot * (1.f / (float)DINNER) + 1e-6f);
    #pragma unroll
    for (int i = 0; i < 6; i++) {
        int d = tid + i * 256;
        g[(size_t)m * DINNER + d] = gv[i] * r * norm_w[d] + res[(size_t)m * DINNER + d];
    }
}

/* --------------------------------- launch ---------------------------------- */
extern "C" void kernel_launch(void* const* d_in, const int* in_sizes, int n_in,
                              void* d_out, int out_size)
{
    (void)in_sizes; (void)n_in; (void)out_size;
    const float* x       = (const float*)d_in[0];
    const float* ln_w    = (const float*)d_in[1];
    const float* ln_b    = (const float*)d_in[2];
    const float* W_in    = (const float*)d_in[3];
    const float* W_dt    = (const float*)d_in[4];
    const float* conv_w  = (const float*)d_in[5];
    const float* conv_b  = (const float*)d_in[6];
    const float* A_log   = (const float*)d_in[7];
    const float* Dskip   = (const float*)d_in[8];
    const float* dt_bias = (const float*)d_in[9];
    const float* norm_w  = (const float*)d_in[10];
    const float* W_res   = (const float*)d_in[11];
    const float* W_out   = (const float*)d_in[12];
    float* out = (float*)d_out;

    float *xn, *p, *dtl, *dtc, *ucb, *yb, *resb, *gb;
    cudaGetSymbolAddress((void**)&xn,   g_xn);
    cudaGetSymbolAddress((void**)&p,    g_p);
    cudaGetSymbolAddress((void**)&dtl,  g_dtl);
    cudaGetSymbolAddress((void**)&dtc,  g_dt);
    cudaGetSymbolAddress((void**)&ucb,  g_uc);
    cudaGetSymbolAddress((void**)&yb,   g_y);
    cudaGetSymbolAddress((void**)&resb, g_res);
    cudaGetSymbolAddress((void**)&gb,   g_g);

    /* 1. layernorm */
    ln_kernel<<<MTOT, 256>>>(x, ln_w, ln_b, xn);

    /* 2. input projection: p = xn @ W_in^T   (2048 x 52272, K=768) */
    gemm_tf32<<<dim3((TOTOUT + 127) / 128, MTOT / 128), 256>>>(
        xn, W_in, p, MTOT, TOTOUT, DMODEL, DMODEL, DMODEL, TOTOUT);

    /* 3. dt linear: dtl = dth @ W_dt^T   (2048 x 1536, K=48), A strided inside p */
    gemm_tf32<<<dim3(DINNER / 128, MTOT / 128), 256>>>(
        p + OFF_DTH, W_dt, dtl, MTOT, DINNER, DTRANK, TOTOUT, DTRANK, DINNER);

    /* 4. softplus/clip + causal depthwise conv */
    prep_kernel<<<MTOT, 256>>>(p, dtl, dt_bias, conv_w, conv_b, dtc, ucb);

    /* 5. selective scan */
    scan_kernel<<<48, 256>>>(p, dtc, ucb, A_log, Dskip, yb);

    /* 6. residual proj: res = x @ W_res^T   (2048 x 1536, K=768) */
    gemm_tf32<<<dim3(DINNER / 128, MTOT / 128), 256>>>(
        x, W_res, resb, MTOT, DINNER, DMODEL, DMODEL, DMODEL, DINNER);

    /* 7. gating + RMS norm + residual add */
    gate_kernel<<<MTOT, 256>>>(yb, p, norm_w, resb, gb);

    /* 8. output proj: out = g @ W_out^T   (2048 x 768, K=1536) */
    gemm_tf32<<<dim3(DMODEL / 128, MTOT / 128), 256>>>(
        gb, W_out, out, MTOT, DMODEL, DINNER, DINNER, DINNER, DMODEL);
}

// round 5
// speedup vs baseline: 1.8860x; 1.8860x over previous
#include <cuda_runtime.h>
#include <cuda_fp16.h>
#include <cstdint>
#include <math.h>

#define BATCH   2
#define SEQL    1024
#define DMODEL  768
#define DINNER  1536
#define DSTATE  16
#define DTRANK  48
#define MTOT    (BATCH*SEQL)
#define TOTOUT  52272
#define OFF_U   DINNER
#define OFF_DTH (2*DINNER)
#define OFF_B   (2*DINNER + DTRANK)
#define OFF_C   (OFF_B + DINNER*DSTATE)

/* ------------------------------ scratch ------------------------------------ */
__device__ float g_p  [(size_t)MTOT * TOTOUT];
__device__ float g_dtl[MTOT * DINNER];
__device__ float g_dt [MTOT * DINNER];
__device__ float g_uc [MTOT * DINNER];
__device__ float g_y  [MTOT * DINNER];
__device__ float g_res[MTOT * DINNER];
__device__ __align__(16) __half g_hXn [MTOT * DMODEL];
__device__ __align__(16) __half g_hX  [MTOT * DMODEL];
__device__ __align__(16) __half g_hG  [MTOT * DINNER];
__device__ __align__(16) __half g_hWin [(size_t)TOTOUT * DMODEL];
__device__ __align__(16) __half g_hWres[DINNER * DMODEL];
__device__ __align__(16) __half g_hWout[DMODEL * DINNER];

/* ------------------------------- helpers ----------------------------------- */
__device__ __forceinline__ float block_sum256(float v, float* sm) {
    int tid = threadIdx.x;
    #pragma unroll
    for (int o = 16; o; o >>= 1) v += __shfl_down_sync(0xffffffffu, v, o);
    if ((tid & 31) == 0) sm[tid >> 5] = v;
    __syncthreads();
    if (tid < 32) {
        float r = (tid < 8) ? sm[tid] : 0.f;
        #pragma unroll
        for (int o = 4; o; o >>= 1) r += __shfl_down_sync(0xffffffffu, r, o);
        if (tid == 0) sm[0] = r;
    }
    __syncthreads();
    float r = sm[0];
    __syncthreads();
    return r;
}

__global__ void h_cvt(const float* __restrict__ src, __half* __restrict__ dst, int n4) {
    int i = blockIdx.x * blockDim.x + threadIdx.x, st = gridDim.x * blockDim.x;
    for (; i < n4; i += st) {
        float4 v = ((const float4*)src)[i];
        __half2 a = __floats2half2_rn(v.x, v.y);
        __half2 b = __floats2half2_rn(v.z, v.w);
        ((__half2*)dst)[2 * i]     = a;
        ((__half2*)dst)[2 * i + 1] = b;
    }
}

__global__ void ln_kernel(const float* __restrict__ x, const float* __restrict__ w,
                          const float* __restrict__ bb, __half* __restrict__ out) {
    __shared__ float sm[8];
    int m = blockIdx.x, tid = threadIdx.x;
    const float* row = x + (size_t)m * DMODEL;
    float v0 = row[tid], v1 = row[tid + 256], v2 = row[tid + 512];
    float s = block_sum256(v0 + v1 + v2, sm);
    float mu = s * (1.f / (float)DMODEL);
    float d0 = v0 - mu, d1 = v1 - mu, d2 = v2 - mu;
    float q = block_sum256(d0 * d0 + d1 * d1 + d2 * d2, sm);
    float inv = rsqrtf(q * (1.f / (float)DMODEL) + 1e-5f);
    __half* o = out + (size_t)m * DMODEL;
    o[tid]       = __float2half_rn(d0 * inv * w[tid]       + bb[tid]);
    o[tid + 256] = __float2half_rn(d1 * inv * w[tid + 256] + bb[tid + 256]);
    o[tid + 512] = __float2half_rn(d2 * inv * w[tid + 512] + bb[tid + 512]);
}

/* ============== fp16 tensor-core GEMM: C[M,N]=A[M,K]*B[N,K]^T ===============
   tile 128x128, BK=64, 256 thr (8 warps, warp tile 64x32), ldmatrix + SW128. */
__global__ void __launch_bounds__(256, 1)
gemm_h(const __half* __restrict__ A, const __half* __restrict__ B,
       float* __restrict__ C, int N, int K, int lda, int ldb, int ldc)
{
    extern __shared__ char smem_raw[];
    const unsigned sraw  = (unsigned)__cvta_generic_to_shared(smem_raw);
    const unsigned sbase = (sraw + 1023u) & ~1023u;

    const int tid = threadIdx.x, lane = tid & 31, warp = tid >> 5;
    const int wm = (warp & 1) * 64, wn = (warp >> 1) * 32;
    const int bm0 = blockIdx.y * 128, bn0 = blockIdx.x * 128;

    float acc[4][4][4];
    #pragma unroll
    for (int i = 0; i < 4; i++)
        #pragma unroll
        for (int j = 0; j < 4; j++)
            #pragma unroll
            for (int k = 0; k < 4; k++) acc[i][j][k] = 0.f;

    /* per-lane ldmatrix address components */
    const int arow  = lane & 15;
    const int abyte = (lane & 16) ? 16 : 0;
    const int brow  = (lane & 7) + ((lane & 16) ? 8 : 0);
    const int bbyte = (lane & 8) ? 16 : 0;

    auto load_stage = [&](int t) {
        unsigned stg = sbase + (unsigned)((t & 1) * 32768);
        int k0 = t * 64;
        #pragma unroll
        for (int i = 0; i < 4; i++) {          /* A: 128 rows x 128B */
            int si = tid * 4 + i;
            int r = si >> 3, sg = si & 7;
            unsigned off = (unsigned)(r * 128 + sg * 16);
            unsigned sw = off ^ ((off >> 3) & 0x70u);
            const __half* g = A + (size_t)(bm0 + r) * lda + k0 + sg * 8;
            asm volatile("cp.async.cg.shared.global [%0], [%1], 16;"
                         :: "r"(stg + sw), "l"(g));
        }
        #pragma unroll
        for (int i = 0; i < 4; i++) {          /* B: 128 rows x 128B */
            int si = tid * 4 + i;
            int r = si >> 3, sg = si & 7;
            int n = bn0 + r;
            unsigned off = (unsigned)(r * 128 + sg * 16);
            unsigned sw = off ^ ((off >> 3) & 0x70u);
            const __half* g = B + (size_t)(n < N ? n : N - 1) * ldb + k0 + sg * 8;
            int bytes = (n < N) ? 16 : 0;
            asm volatile("cp.async.cg.shared.global [%0], [%1], 16, %2;"
                         :: "r"(stg + 16384u + sw), "l"(g), "r"(bytes));
        }
    };

    auto compute_stage = [&](int s) {
        unsigned aB = sbase + (unsigned)((s & 1) * 32768);
        unsigned bB = aB + 16384u;
        #pragma unroll
        for (int ks = 0; ks < 4; ks++) {
            unsigned a[4][4], b[2][4];
            #pragma unroll
            for (int mi = 0; mi < 4; mi++) {
                unsigned off = (unsigned)((wm + mi * 16 + arow) * 128 + ks * 32 + abyte);
                unsigned ad = aB + (off ^ ((off >> 3) & 0x70u));
                asm volatile("ldmatrix.sync.aligned.m8n8.x4.shared.b16 {%0,%1,%2,%3}, [%4];"
                             : "=r"(a[mi][0]), "=r"(a[mi][1]), "=r"(a[mi][2]), "=r"(a[mi][3])
                             : "r"(ad));
            }
            #pragma unroll
            for (int bg = 0; bg < 2; bg++) {
                unsigned off = (unsigned)((wn + bg * 16 + brow) * 128 + ks * 32 + bbyte);
                unsigned ad = bB + (off ^ ((off >> 3) & 0x70u));
                asm volatile("ldmatrix.sync.aligned.m8n8.x4.shared.b16 {%0,%1,%2,%3}, [%4];"
                             : "=r"(b[bg][0]), "=r"(b[bg][1]), "=r"(b[bg][2]), "=r"(b[bg][3])
                             : "r"(ad));
            }
            #pragma unroll
            for (int mi = 0; mi < 4; mi++)
                #pragma unroll
                for (int nj = 0; nj < 4; nj++) {
                    unsigned b0 = b[nj >> 1][(nj & 1) * 2];
                    unsigned b1 = b[nj >> 1][(nj & 1) * 2 + 1];
                    asm volatile(
                        "mma.sync.aligned.m16n8k16.row.col.f32.f16.f16.f32 "
                        "{%0,%1,%2,%3}, {%4,%5,%6,%7}, {%8,%9}, {%0,%1,%2,%3};"
                        : "+f"(acc[mi][nj][0]), "+f"(acc[mi][nj][1]),
                          "+f"(acc[mi][nj][2]), "+f"(acc[mi][nj][3])
                        : "r"(a[mi][0]), "r"(a[mi][1]), "r"(a[mi][2]), "r"(a[mi][3]),
                          "r"(b0), "r"(b1));
                }
        }
    };

    const int nst = K >> 6;
    load_stage(0);
    asm volatile("cp.async.commit_group;");
    for (int kt = 0; kt < nst; kt++) {
        if (kt + 1 < nst) load_stage(kt + 1);
        asm volatile("cp.async.commit_group;");
        asm volatile("cp.async.wait_group 1;");
        __syncthreads();
        compute_stage(kt);
        __syncthreads();
    }

    #pragma unroll
    for (int mi = 0; mi < 4; mi++)
        #pragma unroll
        for (int nj = 0; nj < 4; nj++) {
            int row = bm0 + wm + mi * 16 + (lane >> 2);
            int col = bn0 + wn + nj * 8 + (lane & 3) * 2;
            if (col < N) {
                *(float2*)(C + (size_t)row * ldc + col) =
                    make_float2(acc[mi][nj][0], acc[mi][nj][1]);
                *(float2*)(C + (size_t)(row + 8) * ldc + col) =
                    make_float2(acc[mi][nj][2], acc[mi][nj][3]);
            }
        }
}

/* ---------------- dt projection: fp32 FFMA, K=48, A strided in p ------------ */
__global__ void dtproj_kernel(const float* __restrict__ p, const float* __restrict__ Wdt,
                              float* __restrict__ dtl)
{
    __shared__ float sA[16][48];
    int m0 = blockIdx.x * 16, tid = threadIdx.x;
    for (int i = tid; i < 16 * 48; i += 256)
        sA[i / 48][i % 48] = p[(size_t)(m0 + i / 48) * TOTOUT + OFF_DTH + (i % 48)];
    __syncthreads();
    for (int d = tid; d < DINNER; d += 256) {
        float w[48];
        #pragma unroll
        for (int k = 0; k < 48; k++) w[k] = Wdt[d * 48 + k];
        #pragma unroll
        for (int r = 0; r < 16; r++) {
            float acc = 0.f;
            #pragma unroll
            for (int k = 0; k < 48; k++) acc = fmaf(sA[r][k], w[k], acc);
            dtl[(size_t)(m0 + r) * DINNER + d] = acc;
        }
    }
}

__global__ void prep_kernel(const float* __restrict__ p, const float* __restrict__ dtl,
                            const float* __restrict__ dt_bias, const float* __restrict__ conv_w,
                            const float* __restrict__ conv_b,
                            float* __restrict__ dt_out, float* __restrict__ uc_out)
{
    int m = blockIdx.x, tid = threadIdx.x, l = m & (SEQL - 1);
    #pragma unroll
    for (int i = 0; i < 6; i++) {
        int d = tid + i * 256;
        float xv = dtl[(size_t)m * DINNER + d] + dt_bias[d];
        float sp = (xv > 20.f) ? xv : log1pf(expf(xv));
        dt_out[(size_t)m * DINNER + d] = fminf(fmaxf(sp, 1e-4f), 1.0f);
        float4 cw = *(const float4*)(conv_w + d * 4);
        const float* up = p + OFF_U + d;
        float u0 = (l >= 3) ? up[(size_t)(m - 3) * TOTOUT] : 0.f;
        float u1 = (l >= 2) ? up[(size_t)(m - 2) * TOTOUT] : 0.f;
        float u2 = (l >= 1) ? up[(size_t)(m - 1) * TOTOUT] : 0.f;
        float u3 =            up[(size_t)m * TOTOUT];
        uc_out[(size_t)m * DINNER + d] = conv_b[d] + cw.x*u0 + cw.y*u1 + cw.z*u2 + cw.w*u3;
    }
}

__global__ void scan_kernel(const float* __restrict__ p, const float* __restrict__ dt,
                            const float* __restrict__ uc, const float* __restrict__ A_log,
                            const float* __restrict__ Dskip, float* __restrict__ y)
{
    int t = blockIdx.x * blockDim.x + threadIdx.x;
    int chain = t >> 2, part = t & 3;
    int b = chain / DINNER, d = chain - b * DINNER, n0 = part * 4;
    float a0 = -__expf(A_log[d*DSTATE+n0+0]), a1 = -__expf(A_log[d*DSTATE+n0+1]);
    float a2 = -__expf(A_log[d*DSTATE+n0+2]), a3 = -__expf(A_log[d*DSTATE+n0+3]);
    float dsk = Dskip[d];
    size_t basep = (size_t)b * SEQL * TOTOUT;
    const float* pB = p + basep + OFF_B + d * DSTATE + n0;
    const float* pC = p + basep + OFF_C + d * DSTATE + n0;
    size_t base2 = (size_t)b * SEQL * DINNER + d;
    const float* pdt = dt + base2;
    const float* puc = uc + base2;
    float* py = y + base2;
    float4 Bb[8], Cb[8]; float dtb[8], ucb[8];
    #pragma unroll
    for (int s = 0; s < 8; s++) {
        Bb[s] = *(const float4*)(pB + (size_t)s * TOTOUT);
        Cb[s] = *(const float4*)(pC + (size_t)s * TOTOUT);
        dtb[s] = pdt[(size_t)s * DINNER];
        ucb[s] = puc[(size_t)s * DINNER];
    }
    float h0 = 0.f, h1 = 0.f, h2 = 0.f, h3 = 0.f;
    #pragma unroll 8
    for (int l = 0; l < SEQL; l++) {
        int slot = l & 7;
        float dtv = dtb[slot], ucv = ucb[slot];
        float4 Bv = Bb[slot], Cv = Cb[slot];
        int lp = l + 8;
        if (lp < SEQL) {
            Bb[slot] = *(const float4*)(pB + (size_t)lp * TOTOUT);
            Cb[slot] = *(const float4*)(pC + (size_t)lp * TOTOUT);
            dtb[slot] = pdt[(size_t)lp * DINNER];
            ucb[slot] = puc[(size_t)lp * DINNER];
        }
        float dtu = dtv * ucv;
        h0 = fmaf(h0, __expf(dtv*a0), dtu*Bv.x);
        h1 = fmaf(h1, __expf(dtv*a1), dtu*Bv.y);
        h2 = fmaf(h2, __expf(dtv*a2), dtu*Bv.z);
        h3 = fmaf(h3, __expf(dtv*a3), dtu*Bv.w);
        float acc = Cv.x*h0 + Cv.y*h1 + Cv.z*h2 + Cv.w*h3;
        acc += __shfl_down_sync(0xffffffffu, acc, 2, 4);
        acc += __shfl_down_sync(0xffffffffu, acc, 1, 4);
        if (part == 0) py[(size_t)l * DINNER] = fmaf(ucv, dsk, acc);
    }
}

__global__ void gate_kernel(const float* __restrict__ y, const float* __restrict__ p,
                            const float* __restrict__ norm_w, const float* __restrict__ res,
                            __half* __restrict__ g)
{
    __shared__ float sm[8];
    int m = blockIdx.x, tid = threadIdx.x;
    float gv[6], ss = 0.f;
    #pragma unroll
    for (int i = 0; i < 6; i++) {
        int d = tid + i * 256;
        float z = p[(size_t)m * TOTOUT + d];
        float yv = y[(size_t)m * DINNER + d];
        gv[i] = yv * z / (1.f + __expf(-z));
        ss += gv[i] * gv[i];
    }
    float tot = block_sum256(ss, sm);
    float r = rsqrtf(tot * (1.f / (float)DINNER) + 1e-6f);
    #pragma unroll
    for (int i = 0; i < 6; i++) {
        int d = tid + i * 256;
        g[(size_t)m * DINNER + d] =
            __float2half_rn(gv[i] * r * norm_w[d] + res[(size_t)m * DINNER + d]);
    }
}

/* --------------------------------- launch ---------------------------------- */
extern "C" void kernel_launch(void* const* d_in, const int* in_sizes, int n_in,
                              void* d_out, int out_size)
{
    (void)in_sizes; (void)n_in; (void)out_size;
    const float* x       = (const float*)d_in[0];
    const float* ln_w    = (const float*)d_in[1];
    const float* ln_b    = (const float*)d_in[2];
    const float* W_in    = (const float*)d_in[3];
    const float* W_dt    = (const float*)d_in[4];
    const float* conv_w  = (const float*)d_in[5];
    const float* conv_b  = (const float*)d_in[6];
    const float* A_log   = (const float*)d_in[7];
    const float* Dskip   = (const float*)d_in[8];
    const float* dt_bias = (const float*)d_in[9];
    const float* norm_w  = (const float*)d_in[10];
    const float* W_res   = (const float*)d_in[11];
    const float* W_out   = (const float*)d_in[12];
    float* out = (float*)d_out;

    float *p, *dtl, *dtc, *ucb, *yb, *resb;
    __half *hxn, *hx, *hg, *hwin, *hwres, *hwout;
    cudaGetSymbolAddress((void**)&p,     g_p);
    cudaGetSymbolAddress((void**)&dtl,   g_dtl);
    cudaGetSymbolAddress((void**)&dtc,   g_dt);
    cudaGetSymbolAddress((void**)&ucb,   g_uc);
    cudaGetSymbolAddress((void**)&yb,    g_y);
    cudaGetSymbolAddress((void**)&resb,  g_res);
    cudaGetSymbolAddress((void**)&hxn,   g_hXn);
    cudaGetSymbolAddress((void**)&hx,    g_hX);
    cudaGetSymbolAddress((void**)&hg,    g_hG);
    cudaGetSymbolAddress((void**)&hwin,  g_hWin);
    cudaGetSymbolAddress((void**)&hwres, g_hWres);
    cudaGetSymbolAddress((void**)&hwout, g_hWout);

    const int SMEMSZ = 2 * 32768 + 1024;
    cudaFuncSetAttribute(gemm_h, cudaFuncAttributeMaxDynamicSharedMemorySize, SMEMSZ);

    /* fp16 conversions */
    h_cvt<<<4096, 256>>>(W_in,  hwin,  (int)((size_t)TOTOUT * DMODEL / 4));
    h_cvt<<<512,  256>>>(W_res, hwres, DINNER * DMODEL / 4);
    h_cvt<<<512,  256>>>(W_out, hwout, DMODEL * DINNER / 4);
    h_cvt<<<512,  256>>>(x,     hx,    MTOT * DMODEL / 4);

    ln_kernel<<<MTOT, 256>>>(x, ln_w, ln_b, hxn);

    /* p = xn @ W_in^T : 2048 x 52272, K=768 */
    gemm_h<<<dim3((TOTOUT + 127) / 128, MTOT / 128), 256, SMEMSZ>>>(
        hxn, hwin, p, TOTOUT, DMODEL, DMODEL, DMODEL, TOTOUT);

    dtproj_kernel<<<MTOT / 16, 256>>>(p, W_dt, dtl);
    prep_kernel<<<MTOT, 256>>>(p, dtl, dt_bias, conv_w, conv_b, dtc, ucb);
    scan_kernel<<<48, 256>>>(p, dtc, ucb, A_log, Dskip, yb);

    /* res = x @ W_res^T : 2048 x 1536, K=768 */
    gemm_h<<<dim3(DINNER / 128, MTOT / 128), 256, SMEMSZ>>>(
        hx, hwres, resb, DINNER, DMODEL, DMODEL, DMODEL, DINNER);

    gate_kernel<<<MTOT, 256>>>(yb, p, norm_w, resb, hg);

    /* out = g @ W_out^T : 2048 x 768, K=1536 */
    gemm_h<<<dim3(DMODEL / 128, MTOT / 128), 256, SMEMSZ>>>(
        hg, hwout, out, DMODEL, DINNER, DINNER, DINNER, DMODEL);
}